// round 3
// baseline (speedup 1.0000x reference)
#include <cuda_runtime.h>

// LSTM: B=4096, T=512, I=3, H=32, C=3
// One warp processes NB=4 batch elements; lane l owns hidden unit l.
// W_hh staged to SMEM, permuted for per-lane LDS.128 of the 4 gate weights.
// Packed fp32x2 FMA on the gate pairs (i,f) and (g,o).

#define FULL_MASK 0xffffffffu

constexpr int B_DIM  = 4096;
constexpr int T_DIM  = 512;
constexpr int H_DIM  = 32;
constexpr int NB     = 4;   // batches per warp
constexpr int WARPS  = 4;   // warps per block
constexpr int NTHREADS = WARPS * 32;
constexpr int CHUNK  = 32;  // timesteps of x staged per phase

__device__ __forceinline__ float fast_sigmoid(float x) {
    return __fdividef(1.0f, 1.0f + __expf(-x));
}
__device__ __forceinline__ float fast_tanh(float x) {
    float e = __expf(-2.0f * x);
    return __fdividef(1.0f - e, 1.0f + e);
}
__device__ __forceinline__ unsigned long long pack2(float lo, float hi) {
    unsigned long long r;
    asm("mov.b64 %0, {%1, %2};"
        : "=l"(r) : "r"(__float_as_uint(lo)), "r"(__float_as_uint(hi)));
    return r;
}
__device__ __forceinline__ void unpack2(unsigned long long v, float& lo, float& hi) {
    unsigned int a, b;
    asm("mov.b64 {%0, %1}, %2;" : "=r"(a), "=r"(b) : "l"(v));
    lo = __uint_as_float(a);
    hi = __uint_as_float(b);
}
__device__ __forceinline__ void fma2(unsigned long long& acc,
                                     unsigned long long a,
                                     unsigned long long b) {
    asm("fma.rn.f32x2 %0, %1, %2, %0;" : "+l"(acc) : "l"(a), "l"(b));
}

__global__ void __launch_bounds__(NTHREADS)
lstm_fused_kernel(const float* __restrict__ x,      // (B,T,3)
                  const float* __restrict__ W_ih,   // (128,3)
                  const float* __restrict__ W_hh,   // (128,32)
                  const float* __restrict__ b_ih,   // (128,)
                  const float* __restrict__ b_hh,   // (128,)
                  const float* __restrict__ W_fc,   // (3,32)
                  const float* __restrict__ b_fc,   // (3,)
                  float* __restrict__ out)          // (B,3)
{
    // sW float layout: sW[j*128 + lane*4 + q] = W_hh[(q*32+lane)*32 + j]
    __shared__ float4 sW4[H_DIM * H_DIM];              // 4096 floats = 16 KB
    __shared__ float4 sx4[WARPS * NB * (CHUNK * 3 / 4)]; // 4 warps * 96 f4 = 6 KB

    const int tid  = threadIdx.x;
    const int lane = tid & 31;
    const int warp = tid >> 5;
    const int b0   = (blockIdx.x * WARPS + warp) * NB;

    // ---- stage W_hh (block cooperative) ----
    {
        float* sW = reinterpret_cast<float*>(sW4);
        for (int sidx = tid; sidx < 4 * H_DIM * H_DIM; sidx += NTHREADS) {
            int q  = sidx & 3;
            int ln = (sidx >> 2) & 31;
            int j  = sidx >> 7;
            sW[sidx] = W_hh[(q * 32 + ln) * H_DIM + j];
        }
    }

    // ---- per-lane input weights, combined bias, fc weights ----
    float wih[4][3];
    float bias[4];
#pragma unroll
    for (int q = 0; q < 4; q++) {
        int row = q * 32 + lane;
        wih[q][0] = W_ih[row * 3 + 0];
        wih[q][1] = W_ih[row * 3 + 1];
        wih[q][2] = W_ih[row * 3 + 2];
        bias[q]   = b_ih[row] + b_hh[row];
    }
    const float wfc0 = W_fc[0 * H_DIM + lane];
    const float wfc1 = W_fc[1 * H_DIM + lane];
    const float wfc2 = W_fc[2 * H_DIM + lane];

    __syncthreads();

    float h[NB], c[NB];
#pragma unroll
    for (int n = 0; n < NB; n++) { h[n] = 0.0f; c[n] = 0.0f; }

    const ulonglong2* sWv = reinterpret_cast<const ulonglong2*>(sW4); // [j*32 + lane]
    float4* sxw = sx4 + warp * NB * 24;                 // this warp's x window
    const float* sxf = reinterpret_cast<const float*>(sxw);
    const float4* xv = reinterpret_cast<const float4*>(x);

    for (int tc = 0; tc < T_DIM; tc += CHUNK) {
        // ---- stage x chunk: 4 batches * 24 float4 = 96 float4 per warp ----
        {
            const int cbase = (tc / CHUNK) * 24;  // = tc*3/4
#pragma unroll
            for (int k = 0; k < 3; k++) {
                int idx = lane + k * 32;          // 0..95
                int n = idx / 24, rem = idx % 24;
                sxw[idx] = xv[(size_t)(b0 + n) * (T_DIM * 3 / 4) + cbase + rem];
            }
        }
        __syncwarp();

        for (int tt = 0; tt < CHUNK; tt++) {
            unsigned long long acc01[NB], acc23[NB];
#pragma unroll
            for (int n = 0; n < NB; n++) {
                float x0 = sxf[n * 96 + tt * 3 + 0];
                float x1 = sxf[n * 96 + tt * 3 + 1];
                float x2 = sxf[n * 96 + tt * 3 + 2];
                float a0 = fmaf(x2, wih[0][2], fmaf(x1, wih[0][1], fmaf(x0, wih[0][0], bias[0])));
                float a1 = fmaf(x2, wih[1][2], fmaf(x1, wih[1][1], fmaf(x0, wih[1][0], bias[1])));
                float a2 = fmaf(x2, wih[2][2], fmaf(x1, wih[2][1], fmaf(x0, wih[2][0], bias[2])));
                float a3 = fmaf(x2, wih[3][2], fmaf(x1, wih[3][1], fmaf(x0, wih[3][0], bias[3])));
                acc01[n] = pack2(a0, a1);
                acc23[n] = pack2(a2, a3);
            }

            // recurrent matvec: g += W_hh * h  (packed gate pairs)
#pragma unroll
            for (int j = 0; j < H_DIM; j++) {
                ulonglong2 w = sWv[j * 32 + lane]; // {w_i,w_f} {w_g,w_o} for unit `lane`
#pragma unroll
                for (int n = 0; n < NB; n++) {
                    float hj = __shfl_sync(FULL_MASK, h[n], j);
                    unsigned long long hjj = pack2(hj, hj);
                    fma2(acc01[n], w.x, hjj);
                    fma2(acc23[n], w.y, hjj);
                }
            }

            // gates + cell update
#pragma unroll
            for (int n = 0; n < NB; n++) {
                float ig, fg, gg, og;
                unpack2(acc01[n], ig, fg);
                unpack2(acc23[n], gg, og);
                ig = fast_sigmoid(ig);
                fg = fast_sigmoid(fg);
                gg = fast_tanh(gg);
                og = fast_sigmoid(og);
                c[n] = fmaf(fg, c[n], ig * gg);
                h[n] = og * fast_tanh(c[n]);
            }
        }
        __syncwarp();
    }

    // ---- final FC: out[b,c] = h . W_fc[c,:] + b_fc[c] ----
#pragma unroll
    for (int n = 0; n < NB; n++) {
        float v0 = h[n] * wfc0;
        float v1 = h[n] * wfc1;
        float v2 = h[n] * wfc2;
#pragma unroll
        for (int off = 16; off > 0; off >>= 1) {
            v0 += __shfl_xor_sync(FULL_MASK, v0, off);
            v1 += __shfl_xor_sync(FULL_MASK, v1, off);
            v2 += __shfl_xor_sync(FULL_MASK, v2, off);
        }
        if (lane == 0) {
            out[(b0 + n) * 3 + 0] = v0 + b_fc[0];
            out[(b0 + n) * 3 + 1] = v1 + b_fc[1];
            out[(b0 + n) * 3 + 2] = v2 + b_fc[2];
        }
    }
}

extern "C" void kernel_launch(void* const* d_in, const int* in_sizes, int n_in,
                              void* d_out, int out_size) {
    const float* x    = (const float*)d_in[0];
    const float* W_ih = (const float*)d_in[1];
    const float* W_hh = (const float*)d_in[2];
    const float* b_ih = (const float*)d_in[3];
    const float* b_hh = (const float*)d_in[4];
    const float* W_fc = (const float*)d_in[5];
    const float* b_fc = (const float*)d_in[6];
    float* out = (float*)d_out;

    const int batches_per_block = WARPS * NB;           // 16
    const int grid = B_DIM / batches_per_block;         // 256
    lstm_fused_kernel<<<grid, NTHREADS>>>(x, W_ih, W_hh, b_ih, b_hh, W_fc, b_fc, out);
}